// round 16
// baseline (speedup 1.0000x reference)
#include <cuda_runtime.h>
#include <cuda_bf16.h>
#include <mma.h>
#include <cstdint>

using namespace nvcuda;

// Problem constants
#define B_IMG   64
#define N_OBJ   64
#define M_EDGE  32768
#define OBJDIM  2048
#define QDIM    1024
#define KS      8
#define HID     512
#define HIDKS   4096
#define N2TILES 64                               // GEMM2 N-tiles (width 64)
#define N1TILES 8                                // GEMM1 N-tiles (width 64)

// Scratch (device globals; no cudaMalloc allowed)
__device__ __nv_bfloat16 g_nodeB[(size_t)4096 * OBJDIM];
__device__ __nv_bfloat16 g_WobjB[(size_t)OBJDIM * HID];
__device__ float g_q_h[(size_t)B_IMG * HIDKS];           // [64, 4096]
__device__ float g_P8[(size_t)N1TILES * 4096 * KS];      // per-Ntile P partials
__device__ float g_norm8[(size_t)B_IMG * KS * N2TILES];  // [b][k][ntile]
__device__ int   g_ctr[32];                              // per-Mtile arrival counters (zero-init)

// ---------------------------------------------------------------------------
__device__ __forceinline__ uint32_t smem_u32(const void* p) {
    uint32_t a;
    asm("{ .reg .u64 t; cvta.to.shared.u64 t, %1; cvt.u32.u64 %0, t; }" : "=r"(a) : "l"(p));
    return a;
}
__device__ __forceinline__ void cp_async16(uint32_t dst, const void* src) {
    asm volatile("cp.async.cg.shared.global [%0], [%1], 16;\n" :: "r"(dst), "l"(src));
}
__device__ __forceinline__ void cp_commit() { asm volatile("cp.async.commit_group;\n"); }
template<int N> __device__ __forceinline__ void cp_wait() {
    asm volatile("cp.async.wait_group %0;\n" :: "n"(N));
}
__device__ __forceinline__ void ldsm_x4(uint32_t* r, uint32_t addr) {
    asm volatile("ldmatrix.sync.aligned.m8n8.x4.shared.b16 {%0,%1,%2,%3}, [%4];"
        : "=r"(r[0]), "=r"(r[1]), "=r"(r[2]), "=r"(r[3]) : "r"(addr));
}
__device__ __forceinline__ void ldsm_x4_t(uint32_t* r, uint32_t addr) {
    asm volatile("ldmatrix.sync.aligned.m8n8.x4.trans.shared.b16 {%0,%1,%2,%3}, [%4];"
        : "=r"(r[0]), "=r"(r[1]), "=r"(r[2]), "=r"(r[3]) : "r"(addr));
}
__device__ __forceinline__ void mma_bf16(float* d, const uint32_t* a,
                                         uint32_t b0, uint32_t b1) {
    asm volatile("mma.sync.aligned.m16n8k16.row.col.f32.bf16.bf16.f32 "
        "{%0,%1,%2,%3}, {%4,%5,%6,%7}, {%8,%9}, {%0,%1,%2,%3};"
        : "+f"(d[0]), "+f"(d[1]), "+f"(d[2]), "+f"(d[3])
        : "r"(a[0]), "r"(a[1]), "r"(a[2]), "r"(a[3]), "r"(b0), "r"(b1));
}

// fp32 -> bf16: convert 16 floats (64B read / 32B write) at unit index i
__device__ __forceinline__ void cvt_two(const float* __restrict__ src,
                                        __nv_bfloat16* __restrict__ dst, int i)
{
#pragma unroll
    for (int h = 0; h < 2; h++) {
        float4 v0 = ((const float4*)src)[i * 4 + h * 2];
        float4 v1 = ((const float4*)src)[i * 4 + h * 2 + 1];
        __nv_bfloat162 o0 = __floats2bfloat162_rn(v0.x, v0.y);
        __nv_bfloat162 o1 = __floats2bfloat162_rn(v0.z, v0.w);
        __nv_bfloat162 o2 = __floats2bfloat162_rn(v1.x, v1.y);
        __nv_bfloat162 o3 = __floats2bfloat162_rn(v1.z, v1.w);
        uint4 pack;
        pack.x = *(uint32_t*)&o0; pack.y = *(uint32_t*)&o1;
        pack.z = *(uint32_t*)&o2; pack.w = *(uint32_t*)&o3;
        ((uint4*)dst)[i * 2 + h] = pack;
    }
}

// ---------------------------------------------------------------------------
// K1 (heterogeneous): blocks 0..63 run TF32 GEMM2 directly on fp32 inputs
// (q_h = relu(q_feats @ W_q + b_q), fused norm partials, BM=64 BN=64 BK=32,
// 4 warps, 2-stage cp.async). Blocks 64+ convert node_feats (4096 blocks)
// and W_obj (512 blocks) to bf16, 16 floats/thread. grid = 4672 x 128.
// ---------------------------------------------------------------------------
__global__ __launch_bounds__(128)
void k1_kernel(const float* __restrict__ qf, const float* __restrict__ wq,
               const float* __restrict__ bq, float* __restrict__ qh,
               float* __restrict__ norm8,
               const float* __restrict__ nf, const float* __restrict__ wo,
               __nv_bfloat16* __restrict__ nodeB, __nv_bfloat16* __restrict__ wobjB)
{
    if (blockIdx.x >= N2TILES) {
        const int lb = blockIdx.x - N2TILES;
        if (lb < 4096) cvt_two(nf, nodeB, lb * 128 + threadIdx.x);
        else           cvt_two(wo, wobjB, (lb - 4096) * 128 + threadIdx.x);
        return;
    }

    // ---- TF32 GEMM2 path ----
    constexpr int BM = 64, BN = 64, BK = 32, S = 2;
    constexpr int AP = BK + 4, BP = BN + 4;      // float strides (36, 68)
    constexpr int STAf = BM * AP, STBf = BK * BP;  // 2304, 2176 floats
    constexpr int NIT = QDIM / BK;               // 32
    constexpr int CP = BN + 4;                   // 68

    extern __shared__ __align__(16) float smemf[];
    float* As = smemf;
    float* Bs = smemf + S * STAf;

    const int tid = threadIdx.x;
    const int wid = tid >> 5;
    const int wm = wid & 1, wn = wid >> 1;
    const int bN = blockIdx.x * BN;

    auto load_slab = [&](int slab) {
        const int s = slab & 1, k0 = slab * BK;
#pragma unroll
        for (int t = 0; t < 4; t++) {            // A: 512 float4
            int l = tid + t * 128;
            int r = l >> 3, c = l & 7;
            cp_async16(smem_u32(As + s * STAf + r * AP + c * 4),
                       qf + (size_t)r * QDIM + k0 + c * 4);
        }
#pragma unroll
        for (int t = 0; t < 4; t++) {            // B: 512 float4
            int l = tid + t * 128;
            int r = l >> 4, c = l & 15;
            cp_async16(smem_u32(Bs + s * STBf + r * BP + c * 4),
                       wq + (size_t)(k0 + r) * HIDKS + bN + c * 4);
        }
    };

    wmma::fragment<wmma::accumulator, 16, 16, 8, float> acc[2][2];
#pragma unroll
    for (int i = 0; i < 2; i++)
#pragma unroll
        for (int j = 0; j < 2; j++) wmma::fill_fragment(acc[i][j], 0.0f);

#pragma unroll
    for (int s = 0; s < S; s++) { load_slab(s); cp_commit(); }

    for (int i = 0; i < NIT; i++) {
        cp_wait<0>();
        __syncthreads();
        if (i >= 1) {
            int j = i + 1;
            if (j < NIT) load_slab(j);
            cp_commit();
        }
        const float* as = As + (i & 1) * STAf;
        const float* bs = Bs + (i & 1) * STBf;
#pragma unroll
        for (int kk = 0; kk < BK / 8; kk++) {
            wmma::fragment<wmma::matrix_a, 16, 16, 8, wmma::precision::tf32, wmma::row_major> af[2];
            wmma::fragment<wmma::matrix_b, 16, 16, 8, wmma::precision::tf32, wmma::row_major> bf[2];
#pragma unroll
            for (int f = 0; f < 2; f++) {
                wmma::load_matrix_sync(af[f], as + (wm * 32 + f * 16) * AP + kk * 8, AP);
#pragma unroll
                for (int t = 0; t < af[f].num_elements; t++)
                    af[f].x[t] = wmma::__float_to_tf32(af[f].x[t]);
            }
#pragma unroll
            for (int j = 0; j < 2; j++) {
                wmma::load_matrix_sync(bf[j], bs + (kk * 8) * BP + wn * 32 + j * 16, BP);
#pragma unroll
                for (int t = 0; t < bf[j].num_elements; t++)
                    bf[j].x[t] = wmma::__float_to_tf32(bf[j].x[t]);
            }
#pragma unroll
            for (int f = 0; f < 2; f++)
#pragma unroll
                for (int j = 0; j < 2; j++)
                    wmma::mma_sync(acc[f][j], af[f], bf[j], acc[f][j]);
        }
    }

    __syncthreads();
    float* Cs = smemf;                           // 64 x 68
    float* biasS = Cs + BM * CP;                 // 64
#pragma unroll
    for (int f = 0; f < 2; f++)
#pragma unroll
        for (int j = 0; j < 2; j++)
            wmma::store_matrix_sync(Cs + (wm * 32 + f * 16) * CP + wn * 32 + j * 16,
                                    acc[f][j], CP, wmma::mem_row_major);
    if (tid < BN) biasS[tid] = bq[bN + tid];
    __syncthreads();

    // q_h writes: 64 rows x 64 cols = 1024 float4
#pragma unroll
    for (int t = 0; t < 8; t++) {
        int l = tid + t * 128;
        int r = l >> 4, c4 = (l & 15) * 4;
        float4 v = *(float4*)(Cs + r * CP + c4);
        v.x = fmaxf(v.x + biasS[c4 + 0], 0.0f);
        v.y = fmaxf(v.y + biasS[c4 + 1], 0.0f);
        v.z = fmaxf(v.z + biasS[c4 + 2], 0.0f);
        v.w = fmaxf(v.w + biasS[c4 + 3], 0.0f);
        *(float4*)(qh + (size_t)r * HIDKS + bN + c4) = v;
    }
    // Norm partials, layout [b][k][ntile], ntile = blockIdx.x (64 tiles)
    if (tid < BM) {
        float a[KS];
#pragma unroll
        for (int k = 0; k < KS; k++) a[k] = 0.0f;
#pragma unroll
        for (int c = 0; c < BN; c++) {
            float v = fmaxf(Cs[tid * CP + c] + biasS[c], 0.0f);
            a[c & 7] += v * v;
        }
#pragma unroll
        for (int k = 0; k < KS; k++)
            norm8[(size_t)(tid * KS + k) * N2TILES + blockIdx.x] = a[k];
    }
}

// ---------------------------------------------------------------------------
// GEMM1: mma.sync.m16n8k16 + ldmatrix, S=2, 3 CTAs/SM (24 warps/SM).
// Epilogue contracts the C tile against q_h into P8. The LAST CTA of each
// M-tile then reduces P8+norm8 and emits its 2 batches' 1024 edges.
// ---------------------------------------------------------------------------
__global__ __launch_bounds__(256, 3)
void gemm1_kernel(const __nv_bfloat16* __restrict__ A, const __nv_bfloat16* __restrict__ Bm,
                  const float* __restrict__ bias, const float* __restrict__ qh,
                  float* __restrict__ P8, const float* __restrict__ norm8,
                  const int* __restrict__ idxs, float* __restrict__ out)
{
    constexpr int BM = 128, BN = 64, BK = 64, S = 2;
    constexpr int AP = 72;                                 // bf16 elems (pad 8)
    constexpr int ROWB = AP * 2;                           // 144 B row stride
    constexpr int STA = BM * ROWB, STB = BK * ROWB;        // 18432, 9216
    constexpr int ACH = BM * BK / 8, BCH = BK * BN / 8;    // 1024, 512
    constexpr int PT = (ACH + BCH) / 256;                  // 6
    constexpr int NIT = OBJDIM / BK;                       // 32
    constexpr int CP = BN + 4;                             // 68

    extern __shared__ __align__(16) char smem[];
    const uint32_t sA = smem_u32(smem);
    const uint32_t sB = sA + S * STA;

    const int tid  = threadIdx.x;
    const int wid  = tid >> 5;
    const int lane = tid & 31;
    const int wm = wid & 3, wn = wid >> 2;                 // 4 x 2 warps
    const int bM = blockIdx.y * BM;
    const int bN = blockIdx.x * BN;

    auto load_slab = [&](int slab) {
        const int s = slab % S, k0 = slab * BK;
#pragma unroll
        for (int t = 0; t < PT; t++) {
            int l = tid + t * 256;
            if (l < ACH) {
                int r = l >> 3, c = l & 7;
                cp_async16(sA + s * STA + r * ROWB + c * 16,
                           A + (size_t)(bM + r) * OBJDIM + k0 + c * 8);
            } else {
                int l2 = l - ACH;
                int r = l2 >> 3, c = l2 & 7;
                cp_async16(sB + s * STB + r * ROWB + c * 16,
                           Bm + (size_t)(k0 + r) * HID + bN + c * 8);
            }
        }
    };

    float acc[2][4][4];                                    // [f m16][j n8][4]
#pragma unroll
    for (int f = 0; f < 2; f++)
#pragma unroll
        for (int j = 0; j < 4; j++)
#pragma unroll
            for (int e = 0; e < 4; e++) acc[f][j][e] = 0.0f;

    const uint32_t aLane = (uint32_t)((wm * 32 + (lane & 15)) * ROWB + (lane >> 4) * 16);
    const uint32_t bLane = (uint32_t)((lane & 15) * ROWB + wn * 64 + (lane >> 4) * 16);

#pragma unroll
    for (int s = 0; s < S; s++) { load_slab(s); cp_commit(); }

    for (int i = 0; i < NIT; i++) {
        cp_wait<S - 2>();
        __syncthreads();
        if (i >= 1) {
            int j = i - 1 + S;
            if (j < NIT) load_slab(j);
            cp_commit();
        }
        const uint32_t aSt = sA + (i % S) * STA + aLane;
        const uint32_t bSt = sB + (i % S) * STB + bLane;

        uint32_t Ab[2][2][4];     // [buf][f][4]
        uint32_t Bb[2][2][4];     // [buf][nh][4]
        ldsm_x4(Ab[0][0], aSt);
        ldsm_x4(Ab[0][1], aSt + 16 * ROWB);
        ldsm_x4_t(Bb[0][0], bSt);
        ldsm_x4_t(Bb[0][1], bSt + 32);
#pragma unroll
        for (int kk = 0; kk < 4; kk++) {
            const int cur = kk & 1, nxt = cur ^ 1;
            if (kk < 3) {
                const uint32_t aN = aSt + (kk + 1) * 32;
                const uint32_t bN2 = bSt + (kk + 1) * 16 * ROWB;
                ldsm_x4(Ab[nxt][0], aN);
                ldsm_x4(Ab[nxt][1], aN + 16 * ROWB);
                ldsm_x4_t(Bb[nxt][0], bN2);
                ldsm_x4_t(Bb[nxt][1], bN2 + 32);
            }
#pragma unroll
            for (int f = 0; f < 2; f++) {
                mma_bf16(acc[f][0], Ab[cur][f], Bb[cur][0][0], Bb[cur][0][1]);
                mma_bf16(acc[f][1], Ab[cur][f], Bb[cur][0][2], Bb[cur][0][3]);
                mma_bf16(acc[f][2], Ab[cur][f], Bb[cur][1][0], Bb[cur][1][1]);
                mma_bf16(acc[f][3], Ab[cur][f], Bb[cur][1][2], Bb[cur][1][3]);
            }
        }
    }

    // Epilogue: acc -> Cs, then contract vs q_h into P8 (exclusive writes)
    __syncthreads();
    float* Cs    = (float*)smem;                 // 128 x 68 = 34816 B
    float* qs    = Cs + BM * CP;                 // 1024 floats
    float* biasS = qs + 1024;                    // 64 floats
#pragma unroll
    for (int f = 0; f < 2; f++)
#pragma unroll
        for (int j = 0; j < 4; j++) {
            const int row = wm * 32 + f * 16 + (lane >> 2);
            const int col = wn * 32 + j * 8 + (lane & 3) * 2;
            *(float2*)(Cs + row * CP + col)       = make_float2(acc[f][j][0], acc[f][j][1]);
            *(float2*)(Cs + (row + 8) * CP + col) = make_float2(acc[f][j][2], acc[f][j][3]);
        }
    {   // stage q_h segments for the two batches covered by this M-tile
        const int bB0 = bM >> 6;
        const int s = tid >> 7, i4 = (tid & 127) * 4;
        *(float4*)(qs + s * 512 + i4) =
            *(const float4*)(qh + (size_t)(bB0 + s) * HIDKS + bN * KS + i4);
        if (tid < BN) biasS[tid] = bias[bN + tid];
    }
    __syncthreads();

    // 2 threads per row, 32 cols each; combine via shfl
    {
        const int r = tid >> 1;
        const int ch = (tid & 1) * 32;
        const float* qsp = qs + (r >> 6) * 512;
        float a[KS];
#pragma unroll
        for (int k = 0; k < KS; k++) a[k] = 0.0f;
#pragma unroll 8
        for (int cc = 0; cc < 32; cc++) {
            const int c = ch + cc;
            float v = fmaxf(Cs[r * CP + c] + biasS[c], 0.0f);
            float4 q0 = *(const float4*)(qsp + c * 8);
            float4 q1 = *(const float4*)(qsp + c * 8 + 4);
            a[0] += v * q0.x; a[1] += v * q0.y; a[2] += v * q0.z; a[3] += v * q0.w;
            a[4] += v * q1.x; a[5] += v * q1.y; a[6] += v * q1.z; a[7] += v * q1.w;
        }
#pragma unroll
        for (int k = 0; k < KS; k++)
            a[k] += __shfl_xor_sync(0xFFFFFFFFu, a[k], 1);
        if ((tid & 1) == 0) {
            float* dst = P8 + (size_t)blockIdx.x * (4096 * KS) + (size_t)(bM + r) * KS;
            *(float4*)dst       = make_float4(a[0], a[1], a[2], a[3]);
            *(float4*)(dst + 4) = make_float4(a[4], a[5], a[6], a[7]);
        }
    }

    // ---- last-CTA finalize + gather for this M-tile ----
    __threadfence();                             // make P8 writes visible device-wide
    __shared__ int lastS;
    __syncthreads();                             // all threads' fences done
    if (tid == 0) {
        int old = atomicAdd(&g_ctr[blockIdx.y], 1);
        lastS = (old == N1TILES - 1);
        if (lastS) g_ctr[blockIdx.y] = 0;        // safe: all 8 CTAs have arrived
    }
    __syncthreads();
    if (!lastS) return;

    const int mt = blockIdx.y;
    float* Ps    = (float*)smem;                 // 1024 floats (128 rows x 8 k)
    float* nrmP  = Ps + 1024;                    // 128
    float* invS  = nrmP + 128;                   // 16

    {   // reduce P8 over the 8 N-tiles: 256 float4 slots (128 rows x 2 halves)
        const float4* src = (const float4*)P8;
        const int base = mt * 256;
        float4 s = make_float4(0.f, 0.f, 0.f, 0.f);
#pragma unroll
        for (int nt = 0; nt < N1TILES; nt++) {
            float4 v = src[nt * 8192 + base + tid];
            s.x += v.x; s.y += v.y; s.z += v.z; s.w += v.w;
        }
        ((float4*)Ps)[tid] = s;
    }
    if (tid < 128) {
        // norm8 [b][k][nt], N2TILES=64: pair = (bl,k), part in [0,8) -> 8 floats each
        const int pair = tid >> 3, part = tid & 7;
        const int bl = pair >> 3, k = pair & 7;
        const int b = mt * 2 + bl;
        const float4* s4 = (const float4*)(norm8 + (size_t)(b * KS + k) * N2TILES + part * 8);
        float4 v0 = s4[0], v1 = s4[1];
        nrmP[tid] = v0.x + v0.y + v0.z + v0.w + v1.x + v1.y + v1.z + v1.w;
    }
    __syncthreads();
    if (tid < 16) {
        float s = 0.f;
#pragma unroll
        for (int p = 0; p < 8; p++) s += nrmP[tid * 8 + p];
        invS[tid] = rsqrtf(s);
    }
    __syncthreads();

    // 1024 edges (2 batches), 4 per thread
#pragma unroll
    for (int e4 = 0; e4 < 4; e4++) {
        const int e = tid + e4 * 256;            // [0, 1024)
        const int m = mt * 1024 + e;
        const int bl = e >> 9;
        const int idx = __ldg(idxs + m);
        const int rem = idx & 4095;
        const int sr = rem >> 6, ds = rem & 63;
        const float4* ps = (const float4*)(Ps + (bl * 64 + sr) * KS);
        const float4* pd = (const float4*)(Ps + (bl * 64 + ds) * KS);
        const float4 i0 = *(const float4*)(invS + bl * 8);
        const float4 i1 = *(const float4*)(invS + bl * 8 + 4);
        float4 s0 = ps[0], s1 = ps[1], d0 = pd[0], d1 = pd[1];
        float4 o0 = make_float4((s0.x + d0.x) * i0.x, (s0.y + d0.y) * i0.y,
                                (s0.z + d0.z) * i0.z, (s0.w + d0.w) * i0.w);
        float4 o1 = make_float4((s1.x + d1.x) * i1.x, (s1.y + d1.y) * i1.y,
                                (s1.z + d1.z) * i1.z, (s1.w + d1.w) * i1.w);
        ((float4*)out)[(size_t)m * 2]     = o0;
        ((float4*)out)[(size_t)m * 2 + 1] = o1;
    }
}

// ---------------------------------------------------------------------------
extern "C" void kernel_launch(void* const* d_in, const int* in_sizes, int n_in,
                              void* d_out, int out_size)
{
    const float* node_feats = (const float*)d_in[0];
    const float* q_feats    = (const float*)d_in[1];
    const int*   indexes    = (const int*)d_in[2];
    const float* W_obj      = (const float*)d_in[3];
    const float* b_obj      = (const float*)d_in[4];
    const float* W_q        = (const float*)d_in[5];
    const float* b_q        = (const float*)d_in[6];
    float* out = (float*)d_out;

    __nv_bfloat16 *nodeB, *wobjB;
    float *qh, *P8, *norm8;
    cudaGetSymbolAddress((void**)&nodeB, g_nodeB);
    cudaGetSymbolAddress((void**)&wobjB, g_WobjB);
    cudaGetSymbolAddress((void**)&qh,    g_q_h);
    cudaGetSymbolAddress((void**)&P8,    g_P8);
    cudaGetSymbolAddress((void**)&norm8, g_norm8);

    // K1: TF32 GEMM2 (fp32 inputs, blocks 0..63) + node/W_obj bf16 conversion
    //     (blocks 64..4671) in one heterogeneous launch
    {
        constexpr int SM = 2 * (64 * 36 + 32 * 68) * 4;          // 35840 B
        k1_kernel<<<N2TILES + 4096 + 512, 128, SM>>>(
            q_feats, W_q, b_q, qh, norm8, node_feats, W_obj, nodeB, wobjB);
    }
    // K2: GEMM1 (S=2, 3 CTAs/SM) fused with P contraction + last-CTA finalize/gather
    {
        constexpr int SM = 2 * (128 * 72 * 2 + 64 * 72 * 2);     // 55296
        cudaFuncSetAttribute(gemm1_kernel, cudaFuncAttributeMaxDynamicSharedMemorySize, SM);
        gemm1_kernel<<<dim3(HID / 64, 4096 / 128), 256, SM>>>(
            nodeB, wobjB, b_obj, qh, P8, norm8, indexes, out);
    }
}

// round 17
// speedup vs baseline: 1.3870x; 1.3870x over previous
#include <cuda_runtime.h>
#include <cuda_bf16.h>
#include <mma.h>
#include <cstdint>

using namespace nvcuda;

// Problem constants
#define B_IMG   64
#define N_OBJ   64
#define M_EDGE  32768
#define OBJDIM  2048
#define QDIM    1024
#define KS      8
#define HID     512
#define HIDKS   4096
#define N2TILES 128                              // GEMM2 N-tiles (width 32)
#define N1TILES 8                                // GEMM1 N-tiles (width 64)

// Scratch (device globals; no cudaMalloc allowed)
__device__ __nv_bfloat16 g_nodeB[(size_t)4096 * OBJDIM];
__device__ __nv_bfloat16 g_WobjB[(size_t)OBJDIM * HID];
__device__ float g_q_h[(size_t)B_IMG * HIDKS];           // [64, 4096]
__device__ float g_P8[(size_t)N1TILES * 4096 * KS];      // per-Ntile P partials
__device__ float g_norm8[(size_t)B_IMG * KS * N2TILES];  // [b][k][ntile]
__device__ int   g_ctr[32];                              // per-Mtile arrival counters (zero-init)

// ---------------------------------------------------------------------------
__device__ __forceinline__ uint32_t smem_u32(const void* p) {
    uint32_t a;
    asm("{ .reg .u64 t; cvta.to.shared.u64 t, %1; cvt.u32.u64 %0, t; }" : "=r"(a) : "l"(p));
    return a;
}
__device__ __forceinline__ void cp_async16(uint32_t dst, const void* src) {
    asm volatile("cp.async.cg.shared.global [%0], [%1], 16;\n" :: "r"(dst), "l"(src));
}
__device__ __forceinline__ void cp_commit() { asm volatile("cp.async.commit_group;\n"); }
template<int N> __device__ __forceinline__ void cp_wait() {
    asm volatile("cp.async.wait_group %0;\n" :: "n"(N));
}
__device__ __forceinline__ void ldsm_x4(uint32_t* r, uint32_t addr) {
    asm volatile("ldmatrix.sync.aligned.m8n8.x4.shared.b16 {%0,%1,%2,%3}, [%4];"
        : "=r"(r[0]), "=r"(r[1]), "=r"(r[2]), "=r"(r[3]) : "r"(addr));
}
__device__ __forceinline__ void ldsm_x4_t(uint32_t* r, uint32_t addr) {
    asm volatile("ldmatrix.sync.aligned.m8n8.x4.trans.shared.b16 {%0,%1,%2,%3}, [%4];"
        : "=r"(r[0]), "=r"(r[1]), "=r"(r[2]), "=r"(r[3]) : "r"(addr));
}
__device__ __forceinline__ void mma_bf16(float* d, const uint32_t* a,
                                         uint32_t b0, uint32_t b1) {
    asm volatile("mma.sync.aligned.m16n8k16.row.col.f32.bf16.bf16.f32 "
        "{%0,%1,%2,%3}, {%4,%5,%6,%7}, {%8,%9}, {%0,%1,%2,%3};"
        : "+f"(d[0]), "+f"(d[1]), "+f"(d[2]), "+f"(d[3])
        : "r"(a[0]), "r"(a[1]), "r"(a[2]), "r"(a[3]), "r"(b0), "r"(b1));
}

// float4 -> 4 bf16 packed in uint2 (8 bytes)
__device__ __forceinline__ uint2 cvt4(float4 v) {
    __nv_bfloat162 lo = __floats2bfloat162_rn(v.x, v.y);
    __nv_bfloat162 hi = __floats2bfloat162_rn(v.z, v.w);
    uint2 r;
    r.x = *(uint32_t*)&lo;
    r.y = *(uint32_t*)&hi;
    return r;
}

// fp32 -> bf16: convert 16 floats (64B read / 32B write) at unit index i
__device__ __forceinline__ void cvt_two(const float* __restrict__ src,
                                        __nv_bfloat16* __restrict__ dst, int i)
{
#pragma unroll
    for (int h = 0; h < 2; h++) {
        float4 v0 = ((const float4*)src)[i * 4 + h * 2];
        float4 v1 = ((const float4*)src)[i * 4 + h * 2 + 1];
        uint2 a = cvt4(v0), b = cvt4(v1);
        uint4 pack;
        pack.x = a.x; pack.y = a.y; pack.z = b.x; pack.w = b.y;
        ((uint4*)dst)[i * 2 + h] = pack;
    }
}

// ---------------------------------------------------------------------------
// K1 (heterogeneous, 128 threads, static smem):
//  blocks 0..127:  GEMM2 bf16 wmma, reading fp32 q_feats/W_q via
//                  LDG -> in-register bf16 cvt -> STS (register prefetch
//                  double buffer). q_h = relu(q_feats @ W_q + b_q),
//                  fused norm partials. BM=64 BN=32 BK=64.
//  blocks 128..4735: convert node_feats (4096) + W_obj (512) to bf16,
//                  16 floats per thread.
// ---------------------------------------------------------------------------
__global__ __launch_bounds__(128)
void k1_kernel(const float* __restrict__ qf, const float* __restrict__ wq,
               const float* __restrict__ bq, float* __restrict__ qh,
               float* __restrict__ norm8,
               const float* __restrict__ nf, const float* __restrict__ wo,
               __nv_bfloat16* __restrict__ nodeB, __nv_bfloat16* __restrict__ wobjB)
{
    __shared__ __align__(16) char sm[14464];

    if (blockIdx.x >= N2TILES) {
        const int lb = blockIdx.x - N2TILES;
        if (lb < 4096) cvt_two(nf, nodeB, lb * 128 + threadIdx.x);
        else           cvt_two(wo, wobjB, (lb - 4096) * 128 + threadIdx.x);
        return;
    }

    // ---- GEMM2 path (bf16 MMA, fp32 inputs converted on load) ----
    constexpr int BM = 64, BN = 32, BK = 64;
    constexpr int AP = 72, BP = 40;              // bf16 smem strides
    constexpr int NIT = QDIM / BK;               // 16
    constexpr int CP = BN + 4;                   // 36

    __nv_bfloat16* As = (__nv_bfloat16*)sm;                  // 64 x 72 x 2 = 9216 B
    __nv_bfloat16* Bs = (__nv_bfloat16*)(sm + 9216);         // 64 x 40 x 2 = 5120 B

    const int tid = threadIdx.x;
    const int wid = tid >> 5;
    const int wm = wid & 1, wn = wid >> 1;
    const int bN = blockIdx.x * BN;

    float4 aReg[8], bReg[4];
    auto load_regs = [&](int k0) {
#pragma unroll
        for (int c = 0; c < 8; c++) {            // A: 64x64 fp32, 1024 float4
            int l = tid + c * 128;
            int r = l >> 4, c4 = l & 15;
            aReg[c] = __ldg((const float4*)(qf + (size_t)r * QDIM + k0 + c4 * 4));
        }
#pragma unroll
        for (int c = 0; c < 4; c++) {            // B: 64x32 fp32, 512 float4
            int l = tid + c * 128;
            int r = l >> 3, c4 = l & 7;
            bReg[c] = __ldg((const float4*)(wq + (size_t)(k0 + r) * HIDKS + bN + c4 * 4));
        }
    };
    auto store_regs = [&]() {
#pragma unroll
        for (int c = 0; c < 8; c++) {
            int l = tid + c * 128;
            int r = l >> 4, c4 = l & 15;
            *(uint2*)((char*)As + r * (AP * 2) + c4 * 8) = cvt4(aReg[c]);
        }
#pragma unroll
        for (int c = 0; c < 4; c++) {
            int l = tid + c * 128;
            int r = l >> 3, c4 = l & 7;
            *(uint2*)((char*)Bs + r * (BP * 2) + c4 * 8) = cvt4(bReg[c]);
        }
    };

    wmma::fragment<wmma::accumulator, 16, 16, 16, float> acc[2];
#pragma unroll
    for (int f = 0; f < 2; f++) wmma::fill_fragment(acc[f], 0.0f);

    load_regs(0);
    for (int i = 0; i < NIT; i++) {
        __syncthreads();                         // smem consumers of slab i-1 done
        store_regs();
        if (i + 1 < NIT) load_regs((i + 1) * BK);   // overlaps with wmma below
        __syncthreads();
#pragma unroll
        for (int kk = 0; kk < BK / 16; kk++) {
            wmma::fragment<wmma::matrix_a, 16, 16, 16, __nv_bfloat16, wmma::row_major> af[2];
            wmma::fragment<wmma::matrix_b, 16, 16, 16, __nv_bfloat16, wmma::row_major> bf;
#pragma unroll
            for (int f = 0; f < 2; f++)
                wmma::load_matrix_sync(af[f], As + (wm * 32 + f * 16) * AP + kk * 16, AP);
            wmma::load_matrix_sync(bf, Bs + (kk * 16) * BP + wn * 16, BP);
#pragma unroll
            for (int f = 0; f < 2; f++)
                wmma::mma_sync(acc[f], af[f], bf, acc[f]);
        }
    }

    __syncthreads();
    float* Cs = (float*)sm;                      // 64 x 36 floats = 9216 B
    float* biasS = Cs + BM * CP;                 // 32 floats
#pragma unroll
    for (int f = 0; f < 2; f++)
        wmma::store_matrix_sync(Cs + (wm * 32 + f * 16) * CP + wn * 16,
                                acc[f], CP, wmma::mem_row_major);
    if (tid < BN) biasS[tid] = bq[bN + tid];
    __syncthreads();

    // q_h writes: 64 rows x 32 cols = 512 float4
#pragma unroll
    for (int t = 0; t < 4; t++) {
        int l = tid + t * 128;
        int r = l >> 3, c4 = (l & 7) * 4;
        float4 v = *(float4*)(Cs + r * CP + c4);
        v.x = fmaxf(v.x + biasS[c4 + 0], 0.0f);
        v.y = fmaxf(v.y + biasS[c4 + 1], 0.0f);
        v.z = fmaxf(v.z + biasS[c4 + 2], 0.0f);
        v.w = fmaxf(v.w + biasS[c4 + 3], 0.0f);
        *(float4*)(qh + (size_t)r * HIDKS + bN + c4) = v;
    }
    // Norm partials, layout [b][k][ntile]
    if (tid < BM) {
        float a[KS];
#pragma unroll
        for (int k = 0; k < KS; k++) a[k] = 0.0f;
#pragma unroll
        for (int c = 0; c < BN; c++) {
            float v = fmaxf(Cs[tid * CP + c] + biasS[c], 0.0f);
            a[c & 7] += v * v;
        }
#pragma unroll
        for (int k = 0; k < KS; k++)
            norm8[(size_t)(tid * KS + k) * N2TILES + blockIdx.x] = a[k];
    }
}

// ---------------------------------------------------------------------------
// GEMM1: mma.sync.m16n8k16 + ldmatrix, S=2, 3 CTAs/SM (24 warps/SM).
// Epilogue contracts the C tile against q_h into P8. The LAST CTA of each
// M-tile then reduces P8+norm8 and emits its 2 batches' 1024 edges.
// ---------------------------------------------------------------------------
__global__ __launch_bounds__(256, 3)
void gemm1_kernel(const __nv_bfloat16* __restrict__ A, const __nv_bfloat16* __restrict__ Bm,
                  const float* __restrict__ bias, const float* __restrict__ qh,
                  float* __restrict__ P8, const float* __restrict__ norm8,
                  const int* __restrict__ idxs, float* __restrict__ out)
{
    constexpr int BM = 128, BN = 64, BK = 64, S = 2;
    constexpr int AP = 72;                                 // bf16 elems (pad 8)
    constexpr int ROWB = AP * 2;                           // 144 B row stride
    constexpr int STA = BM * ROWB, STB = BK * ROWB;        // 18432, 9216
    constexpr int ACH = BM * BK / 8, BCH = BK * BN / 8;    // 1024, 512
    constexpr int PT = (ACH + BCH) / 256;                  // 6
    constexpr int NIT = OBJDIM / BK;                       // 32
    constexpr int CP = BN + 4;                             // 68

    extern __shared__ __align__(16) char smem[];
    const uint32_t sA = smem_u32(smem);
    const uint32_t sB = sA + S * STA;

    const int tid  = threadIdx.x;
    const int wid  = tid >> 5;
    const int lane = tid & 31;
    const int wm = wid & 3, wn = wid >> 2;                 // 4 x 2 warps
    const int bM = blockIdx.y * BM;
    const int bN = blockIdx.x * BN;

    auto load_slab = [&](int slab) {
        const int s = slab % S, k0 = slab * BK;
#pragma unroll
        for (int t = 0; t < PT; t++) {
            int l = tid + t * 256;
            if (l < ACH) {
                int r = l >> 3, c = l & 7;
                cp_async16(sA + s * STA + r * ROWB + c * 16,
                           A + (size_t)(bM + r) * OBJDIM + k0 + c * 8);
            } else {
                int l2 = l - ACH;
                int r = l2 >> 3, c = l2 & 7;
                cp_async16(sB + s * STB + r * ROWB + c * 16,
                           Bm + (size_t)(k0 + r) * HID + bN + c * 8);
            }
        }
    };

    float acc[2][4][4];                                    // [f m16][j n8][4]
#pragma unroll
    for (int f = 0; f < 2; f++)
#pragma unroll
        for (int j = 0; j < 4; j++)
#pragma unroll
            for (int e = 0; e < 4; e++) acc[f][j][e] = 0.0f;

    const uint32_t aLane = (uint32_t)((wm * 32 + (lane & 15)) * ROWB + (lane >> 4) * 16);
    const uint32_t bLane = (uint32_t)((lane & 15) * ROWB + wn * 64 + (lane >> 4) * 16);

#pragma unroll
    for (int s = 0; s < S; s++) { load_slab(s); cp_commit(); }

    for (int i = 0; i < NIT; i++) {
        cp_wait<S - 2>();
        __syncthreads();
        if (i >= 1) {
            int j = i - 1 + S;
            if (j < NIT) load_slab(j);
            cp_commit();
        }
        const uint32_t aSt = sA + (i % S) * STA + aLane;
        const uint32_t bSt = sB + (i % S) * STB + bLane;

        uint32_t Ab[2][2][4];     // [buf][f][4]
        uint32_t Bb[2][2][4];     // [buf][nh][4]
        ldsm_x4(Ab[0][0], aSt);
        ldsm_x4(Ab[0][1], aSt + 16 * ROWB);
        ldsm_x4_t(Bb[0][0], bSt);
        ldsm_x4_t(Bb[0][1], bSt + 32);
#pragma unroll
        for (int kk = 0; kk < 4; kk++) {
            const int cur = kk & 1, nxt = cur ^ 1;
            if (kk < 3) {
                const uint32_t aN = aSt + (kk + 1) * 32;
                const uint32_t bN2 = bSt + (kk + 1) * 16 * ROWB;
                ldsm_x4(Ab[nxt][0], aN);
                ldsm_x4(Ab[nxt][1], aN + 16 * ROWB);
                ldsm_x4_t(Bb[nxt][0], bN2);
                ldsm_x4_t(Bb[nxt][1], bN2 + 32);
            }
#pragma unroll
            for (int f = 0; f < 2; f++) {
                mma_bf16(acc[f][0], Ab[cur][f], Bb[cur][0][0], Bb[cur][0][1]);
                mma_bf16(acc[f][1], Ab[cur][f], Bb[cur][0][2], Bb[cur][0][3]);
                mma_bf16(acc[f][2], Ab[cur][f], Bb[cur][1][0], Bb[cur][1][1]);
                mma_bf16(acc[f][3], Ab[cur][f], Bb[cur][1][2], Bb[cur][1][3]);
            }
        }
    }

    // Epilogue: acc -> Cs, then contract vs q_h into P8 (exclusive writes)
    __syncthreads();
    float* Cs    = (float*)smem;                 // 128 x 68 = 34816 B
    float* qs    = Cs + BM * CP;                 // 1024 floats
    float* biasS = qs + 1024;                    // 64 floats
#pragma unroll
    for (int f = 0; f < 2; f++)
#pragma unroll
        for (int j = 0; j < 4; j++) {
            const int row = wm * 32 + f * 16 + (lane >> 2);
            const int col = wn * 32 + j * 8 + (lane & 3) * 2;
            *(float2*)(Cs + row * CP + col)       = make_float2(acc[f][j][0], acc[f][j][1]);
            *(float2*)(Cs + (row + 8) * CP + col) = make_float2(acc[f][j][2], acc[f][j][3]);
        }
    {   // stage q_h segments for the two batches covered by this M-tile
        const int bB0 = bM >> 6;
        const int s = tid >> 7, i4 = (tid & 127) * 4;
        *(float4*)(qs + s * 512 + i4) =
            *(const float4*)(qh + (size_t)(bB0 + s) * HIDKS + bN * KS + i4);
        if (tid < BN) biasS[tid] = bias[bN + tid];
    }
    __syncthreads();

    // 2 threads per row, 32 cols each; combine via shfl
    {
        const int r = tid >> 1;
        const int ch = (tid & 1) * 32;
        const float* qsp = qs + (r >> 6) * 512;
        float a[KS];
#pragma unroll
        for (int k = 0; k < KS; k++) a[k] = 0.0f;
#pragma unroll 8
        for (int cc = 0; cc < 32; cc++) {
            const int c = ch + cc;
            float v = fmaxf(Cs[r * CP + c] + biasS[c], 0.0f);
            float4 q0 = *(const float4*)(qsp + c * 8);
            float4 q1 = *(const float4*)(qsp + c * 8 + 4);
            a[0] += v * q0.x; a[1] += v * q0.y; a[2] += v * q0.z; a[3] += v * q0.w;
            a[4] += v * q1.x; a[5] += v * q1.y; a[6] += v * q1.z; a[7] += v * q1.w;
        }
#pragma unroll
        for (int k = 0; k < KS; k++)
            a[k] += __shfl_xor_sync(0xFFFFFFFFu, a[k], 1);
        if ((tid & 1) == 0) {
            float* dst = P8 + (size_t)blockIdx.x * (4096 * KS) + (size_t)(bM + r) * KS;
            *(float4*)dst       = make_float4(a[0], a[1], a[2], a[3]);
            *(float4*)(dst + 4) = make_float4(a[4], a[5], a[6], a[7]);
        }
    }

    // ---- last-CTA finalize + gather for this M-tile ----
    __threadfence();                             // make P8 writes visible device-wide
    __shared__ int lastS;
    __syncthreads();                             // all threads' fences done
    if (tid == 0) {
        int old = atomicAdd(&g_ctr[blockIdx.y], 1);
        lastS = (old == N1TILES - 1);
        if (lastS) g_ctr[blockIdx.y] = 0;        // safe: all 8 CTAs have arrived
    }
    __syncthreads();
    if (!lastS) return;

    const int mt = blockIdx.y;
    float* Ps    = (float*)smem;                 // 1024 floats (128 rows x 8 k)
    float* nrmP  = Ps + 1024;                    // 128
    float* invS  = nrmP + 128;                   // 16

    {   // reduce P8 over the 8 N-tiles: 256 float4 slots (128 rows x 2 halves)
        const float4* src = (const float4*)P8;
        const int base = mt * 256;
        float4 s = make_float4(0.f, 0.f, 0.f, 0.f);
#pragma unroll
        for (int nt = 0; nt < N1TILES; nt++) {
            float4 v = src[nt * 8192 + base + tid];
            s.x += v.x; s.y += v.y; s.z += v.z; s.w += v.w;
        }
        ((float4*)Ps)[tid] = s;
    }
    if (tid < 128) {
        // norm8 [b][k][nt]: pair = (bl,k) in [0,16), part in [0,8) -> 16 floats each
        const int pair = tid >> 3, part = tid & 7;
        const int bl = pair >> 3, k = pair & 7;
        const int b = mt * 2 + bl;
        const float4* s4 = (const float4*)(norm8 + (size_t)(b * KS + k) * N2TILES + part * 16);
        float4 v0 = s4[0], v1 = s4[1], v2 = s4[2], v3 = s4[3];
        nrmP[tid] = v0.x + v0.y + v0.z + v0.w + v1.x + v1.y + v1.z + v1.w
                  + v2.x + v2.y + v2.z + v2.w + v3.x + v3.y + v3.z + v3.w;
    }
    __syncthreads();
    if (tid < 16) {
        float s = 0.f;
#pragma unroll
        for (int p = 0; p < 8; p++) s += nrmP[tid * 8 + p];
        invS[tid] = rsqrtf(s);
    }
    __syncthreads();

    // 1024 edges (2 batches), 4 per thread
#pragma unroll
    for (int e4 = 0; e4 < 4; e4++) {
        const int e = tid + e4 * 256;            // [0, 1024)
        const int m = mt * 1024 + e;
        const int bl = e >> 9;
        const int idx = __ldg(idxs + m);
        const int rem = idx & 4095;
        const int sr = rem >> 6, ds = rem & 63;
        const float4* ps = (const float4*)(Ps + (bl * 64 + sr) * KS);
        const float4* pd = (const float4*)(Ps + (bl * 64 + ds) * KS);
        const float4 i0 = *(const float4*)(invS + bl * 8);
        const float4 i1 = *(const float4*)(invS + bl * 8 + 4);
        float4 s0 = ps[0], s1 = ps[1], d0 = pd[0], d1 = pd[1];
        float4 o0 = make_float4((s0.x + d0.x) * i0.x, (s0.y + d0.y) * i0.y,
                                (s0.z + d0.z) * i0.z, (s0.w + d0.w) * i0.w);
        float4 o1 = make_float4((s1.x + d1.x) * i1.x, (s1.y + d1.y) * i1.y,
                                (s1.z + d1.z) * i1.z, (s1.w + d1.w) * i1.w);
        ((float4*)out)[(size_t)m * 2]     = o0;
        ((float4*)out)[(size_t)m * 2 + 1] = o1;
    }
}

// ---------------------------------------------------------------------------
extern "C" void kernel_launch(void* const* d_in, const int* in_sizes, int n_in,
                              void* d_out, int out_size)
{
    const float* node_feats = (const float*)d_in[0];
    const float* q_feats    = (const float*)d_in[1];
    const int*   indexes    = (const int*)d_in[2];
    const float* W_obj      = (const float*)d_in[3];
    const float* b_obj      = (const float*)d_in[4];
    const float* W_q        = (const float*)d_in[5];
    const float* b_q        = (const float*)d_in[6];
    float* out = (float*)d_out;

    __nv_bfloat16 *nodeB, *wobjB;
    float *qh, *P8, *norm8;
    cudaGetSymbolAddress((void**)&nodeB, g_nodeB);
    cudaGetSymbolAddress((void**)&wobjB, g_WobjB);
    cudaGetSymbolAddress((void**)&qh,    g_q_h);
    cudaGetSymbolAddress((void**)&P8,    g_P8);
    cudaGetSymbolAddress((void**)&norm8, g_norm8);

    // K1: GEMM2 (bf16 MMA on fp32 inputs, blocks 0..127) + node/W_obj
    //     bf16 conversion (blocks 128..4735), one heterogeneous launch
    k1_kernel<<<N2TILES + 4096 + 512, 128>>>(
        q_feats, W_q, b_q, qh, norm8, node_feats, W_obj, nodeB, wobjB);

    // K2: GEMM1 (S=2, 3 CTAs/SM) fused with P contraction + last-CTA finalize/gather
    {
        constexpr int SM = 2 * (128 * 72 * 2 + 64 * 72 * 2);     // 55296
        cudaFuncSetAttribute(gemm1_kernel, cudaFuncAttributeMaxDynamicSharedMemorySize, SM);
        gemm1_kernel<<<dim3(HID / 64, 4096 / 128), 256, SM>>>(
            nodeB, wobjB, b_obj, qh, P8, norm8, indexes, out);
    }
}